// round 11
// baseline (speedup 1.0000x reference)
#include <cuda_runtime.h>
#include <cstdint>

#define BN 512
#define NSTEPS 100

// ---------------- persistent device state (allocation-free scratch) ----------------
__device__ float    g_m1 [BN * 20 * 784];  // conv1 membrane
__device__ float    g_m1s[BN * 20 * 196];  // pool1 membrane
__device__ uint32_t g_opm[BN * 196];       // pool1 output spike masks (bit ci)
__device__ float    g_m2 [BN * 50 * 196];  // conv2 membrane
__device__ float    g_m2s[BN * 50 * 49];   // pool2 membrane
__device__ uint32_t g_op2m[BN][2][40];     // pool2 spike masks: region cb, 39 words (k=cb*1225+w*32+j)
__device__ float    g_mf0[BN * 200];       // fc0 membrane
__device__ float    g_tf0[BN * 200];       // fc0 total spike count (ONLY output that matters)
__device__ float    g_w2t [2 * 500 * 26];  // conv2 weights pre-transposed [cb][kk*20+ci][ch pad26]
__device__ float    g_wf0T[2450 * 200];    // wf0 transposed [k][n]

// ---------------- Threefry-2x32, 20 rounds (matches JAX exactly) ----------------
__host__ __device__ __forceinline__ void tf2x32(uint32_t k0, uint32_t k1,
                                                uint32_t x0, uint32_t x1,
                                                uint32_t& o0, uint32_t& o1) {
    uint32_t k2 = k0 ^ k1 ^ 0x1BD11BDAu;
    x0 += k0; x1 += k1;
#define TFR(r) { x0 += x1; x1 = (x1 << (r)) | (x1 >> (32 - (r))); x1 ^= x0; }
    TFR(13) TFR(15) TFR(26) TFR(6)   x0 += k1; x1 += k2 + 1u;
    TFR(17) TFR(29) TFR(16) TFR(24)  x0 += k2; x1 += k0 + 2u;
    TFR(13) TFR(15) TFR(26) TFR(6)   x0 += k0; x1 += k1 + 3u;
    TFR(17) TFR(29) TFR(16) TFR(24)  x0 += k1; x1 += k2 + 4u;
    TFR(13) TFR(15) TFR(26) TFR(6)   x0 += k2; x1 += k0 + 5u;
#undef TFR
    o0 = x0; o1 = x1;
}

// ---------------- one-time prep: transpose w2 and wf0 (runs once per launch, in-graph) ----------------
__global__ void k_prep(const float* __restrict__ w2, const float* __restrict__ wf0) {
    int i = blockIdx.x * blockDim.x + threadIdx.x;
    // g_w2t[(cb*500 + kk*20+ci)*26 + ch] = w2[(cb*25+ch)*500 + ci*25 + kk]
    if (i < 2 * 500 * 26) {
        int ch = i % 26, rem = i / 26, kkci = rem % 500, cb = rem / 500;
        int kk = kkci / 20, ci = kkci % 20;
        g_w2t[i] = (ch < 25) ? w2[(cb * 25 + ch) * 500 + ci * 25 + kk] : 0.f;
    }
    // g_wf0T[k*200+n] = wf0[n*2450+k]
    int j = i - 2 * 500 * 26;
    if (j >= 0 && j < 2450 * 200) {
        int n = j % 200, k = j / 200;
        g_wf0T[j] = wf0[n * 2450 + k];
    }
}

// ---------------- conv1 (RNG fused) + fire(1.0) + avgpool2 + fire(0.75) ----------------
// grid (b, 2 row-halves). Block `half` computes pooled rows [7*half, 7*half+7),
// needing input rows [14*half-2, 14*half+16) -> RNG over 448 pixels only.
// All chains and spike indices identical to the single-block form (bit-exact).
__global__ __launch_bounds__(224) void k_conv1(const float* __restrict__ in,
                                               const float* __restrict__ w1,
                                               uint32_t k0, uint32_t k1) {
    int b = blockIdx.x;
    int half = blockIdx.y;
    int rbase = half * 14;          // first output row handled by this block
    int glo = rbase - 2;            // global input row at local smem row 0
    __shared__ float sin_[18][32];  // local rows 0..17, cols 2..29 valid
    __shared__ float sw[500];       // 20 x 25 weights
    int t = threadIdx.x;
    for (int i = t; i < 18 * 32; i += 224) ((float*)sin_)[i] = 0.f;
    for (int i = t; i < 500;  i += 224) sw[i] = w1[i];
    __syncthreads();
    // RNG for input rows [r0g, r0g+16): half 0 -> 0..15, half 1 -> 12..27
    int r0g = (half == 0) ? 0 : 12;
    for (int i = t; i < 448; i += 224) {
        int r = r0g + i / 28, c = i % 28;
        int px_idx = b * 784 + r * 28 + c;
        uint32_t o0, o1;
        tf2x32(k0, k1, 0u, (uint32_t)px_idx, o0, o1);
        uint32_t bits = o0 ^ o1;
        float u = __uint_as_float((bits >> 9) | 0x3f800000u) - 1.0f;
        float v = in[px_idx];
        float sgn = (v > 0.f) ? 1.f : ((v < 0.f) ? -1.f : 0.f);
        sin_[r - glo][2 + c] = (fabsf(v) * 0.5f > u) ? sgn : 0.f;
    }
    __syncthreads();

    if (t < 98) {
        int py = t / 14, px = t % 14;   // local pooled row 0..6
        int c0 = 2 * px;
        // local patch row for output row (rbase+2*py) is exactly 2*py (glo = rbase-2)
        float p[6][6];
#pragma unroll
        for (int r = 0; r < 6; r++)
#pragma unroll
            for (int c = 0; c < 6; c++) p[r][c] = sin_[2 * py + r][c0 + c];

        uint32_t mask = 0u;
        for (int ch = 0; ch < 20; ch++) {
            const float* w = &sw[ch * 25];
            float a00 = 0.f, a01 = 0.f, a10 = 0.f, a11 = 0.f;
#pragma unroll
            for (int ky = 0; ky < 5; ky++)
#pragma unroll
                for (int kx = 0; kx < 5; kx++) {
                    float wv = w[ky * 5 + kx];
                    a00 = __fmaf_rn(p[ky][kx],         wv, a00);
                    a01 = __fmaf_rn(p[ky][kx + 1],     wv, a01);
                    a10 = __fmaf_rn(p[ky + 1][kx],     wv, a10);
                    a11 = __fmaf_rn(p[ky + 1][kx + 1], wv, a11);
                }
            size_t mb = (size_t)(b * 20 + ch) * 784;
            int i00 = (rbase + 2 * py) * 28 + c0;
            float m00 = g_m1[mb + i00]      + a00;
            float m01 = g_m1[mb + i00 + 1]  + a01;
            float m10 = g_m1[mb + i00 + 28] + a10;
            float m11 = g_m1[mb + i00 + 29] + a11;
            float f00 = (m00 > 1.f) ? 1.f : 0.f; g_m1[mb + i00]      = (m00 > 1.f) ? 0.f : m00;
            float f01 = (m01 > 1.f) ? 1.f : 0.f; g_m1[mb + i00 + 1]  = (m01 > 1.f) ? 0.f : m01;
            float f10 = (m10 > 1.f) ? 1.f : 0.f; g_m1[mb + i00 + 28] = (m10 > 1.f) ? 0.f : m10;
            float f11 = (m11 > 1.f) ? 1.f : 0.f; g_m1[mb + i00 + 29] = (m11 > 1.f) ? 0.f : m11;
            int pi = (b * 20 + ch) * 196 + half * 98 + t;
            float ms = g_m1s[pi] + 0.25f * (f00 + f01 + f10 + f11);
            if (ms > 0.75f) { mask |= (1u << ch); g_m1s[pi] = 0.f; }
            else            { g_m1s[pi] = ms; }
        }
        g_opm[b * 196 + half * 98 + t] = mask;
    }
}

// ---------------- conv2 SPARSE, 1 image/block; emits pool2 bit-masks ----------------
// grid (BN, 2). 256 threads = 5 cogs x 49 positions, 5 ch/thread. Inner chain = round-8 exact.
#define C2_SMEM ((364 + 13000) * 4)
__global__ __launch_bounds__(256) void k_conv2() {
    extern __shared__ unsigned char dynv[];
    uint32_t* sm    = (uint32_t*)dynv;               // 18x18 spike masks (halo zero)
    uint32_t* smask = (uint32_t*)dynv + 324;         // 40-word output mask
    float*    swt   = (float*)(dynv + 364 * 4);      // [kk][ci][ch] slot 26
    int b  = blockIdx.x;
    int cb = blockIdx.y;
    int t = threadIdx.x;
    // stage weights: pure float4 copy from pre-transposed global (L2-resident)
    {
        const float4* src = (const float4*)(g_w2t + cb * 13000);
        float4* dst = (float4*)swt;
        for (int i = t; i < 3250; i += 256) dst[i] = src[i];
    }
    for (int i = t; i < 324; i += 256) {
        int rr = i / 18 - 2, cc = i % 18 - 2;
        sm[i] = (rr >= 0 && rr < 14 && cc >= 0 && cc < 14) ? g_opm[b * 196 + rr * 14 + cc] : 0u;
    }
    if (t < 40) smask[t] = 0u;
    __syncthreads();

    if (t < 245) {
        int cog = t / 49, q = t % 49;
        int py = q / 7, px = q % 7;
        int r0 = 2 * py, c0 = 2 * px;
        float acc[5][4] = {};
#pragma unroll 1
        for (int ky = 0; ky < 5; ky++) {
            const uint32_t* mr0 = &sm[(r0 + ky) * 18 + c0];
            const uint32_t* mr1 = mr0 + 18;
#pragma unroll 1
            for (int kx = 0; kx < 5; kx++) {
                uint32_t m0 = mr0[kx], m1 = mr0[kx + 1];
                uint32_t m2 = mr1[kx], m3 = mr1[kx + 1];
                const float* wk = &swt[(ky * 5 + kx) * 20 * 26 + cog * 5];
                while (m0) {
                    int ci = __ffs(m0) - 1; m0 &= m0 - 1;
                    const float* w = wk + ci * 26;
                    acc[0][0] = __fadd_rn(acc[0][0], w[0]);
                    acc[1][0] = __fadd_rn(acc[1][0], w[1]);
                    acc[2][0] = __fadd_rn(acc[2][0], w[2]);
                    acc[3][0] = __fadd_rn(acc[3][0], w[3]);
                    acc[4][0] = __fadd_rn(acc[4][0], w[4]);
                }
                while (m1) {
                    int ci = __ffs(m1) - 1; m1 &= m1 - 1;
                    const float* w = wk + ci * 26;
                    acc[0][1] = __fadd_rn(acc[0][1], w[0]);
                    acc[1][1] = __fadd_rn(acc[1][1], w[1]);
                    acc[2][1] = __fadd_rn(acc[2][1], w[2]);
                    acc[3][1] = __fadd_rn(acc[3][1], w[3]);
                    acc[4][1] = __fadd_rn(acc[4][1], w[4]);
                }
                while (m2) {
                    int ci = __ffs(m2) - 1; m2 &= m2 - 1;
                    const float* w = wk + ci * 26;
                    acc[0][2] = __fadd_rn(acc[0][2], w[0]);
                    acc[1][2] = __fadd_rn(acc[1][2], w[1]);
                    acc[2][2] = __fadd_rn(acc[2][2], w[2]);
                    acc[3][2] = __fadd_rn(acc[3][2], w[3]);
                    acc[4][2] = __fadd_rn(acc[4][2], w[4]);
                }
                while (m3) {
                    int ci = __ffs(m3) - 1; m3 &= m3 - 1;
                    const float* w = wk + ci * 26;
                    acc[0][3] = __fadd_rn(acc[0][3], w[0]);
                    acc[1][3] = __fadd_rn(acc[1][3], w[1]);
                    acc[2][3] = __fadd_rn(acc[2][3], w[2]);
                    acc[3][3] = __fadd_rn(acc[3][3], w[3]);
                    acc[4][3] = __fadd_rn(acc[4][3], w[4]);
                }
            }
        }
#pragma unroll
        for (int u = 0; u < 5; u++) {
            int colocal = cog * 5 + u;
            int co = cb * 25 + colocal;
            size_t mb = (size_t)(b * 50 + co) * 196;
            int i00 = r0 * 14 + c0;
            float m00 = g_m2[mb + i00]      + acc[u][0];
            float m01 = g_m2[mb + i00 + 1]  + acc[u][1];
            float m10 = g_m2[mb + i00 + 14] + acc[u][2];
            float m11 = g_m2[mb + i00 + 15] + acc[u][3];
            float f00 = (m00 > 1.f) ? 1.f : 0.f; g_m2[mb + i00]      = (m00 > 1.f) ? 0.f : m00;
            float f01 = (m01 > 1.f) ? 1.f : 0.f; g_m2[mb + i00 + 1]  = (m01 > 1.f) ? 0.f : m01;
            float f10 = (m10 > 1.f) ? 1.f : 0.f; g_m2[mb + i00 + 14] = (m10 > 1.f) ? 0.f : m10;
            float f11 = (m11 > 1.f) ? 1.f : 0.f; g_m2[mb + i00 + 15] = (m11 > 1.f) ? 0.f : m11;
            int pi = (b * 50 + co) * 49 + q;
            float ms = g_m2s[pi] + 0.25f * (f00 + f01 + f10 + f11);
            if (ms > 0.75f) {
                g_m2s[pi] = 0.f;
                int bit = colocal * 49 + q;
                atomicOr(&smask[bit >> 5], 1u << (bit & 31));
            } else {
                g_m2s[pi] = ms;
            }
        }
    }
    __syncthreads();
    if (t < 39) g_op2m[b][cb][t] = smask[t];
}

// ---------------- fc0 SPARSE: acc = sum of wf0T[k][n] over set k ascending; fire fused ----------------
__global__ __launch_bounds__(256) void k_fc0s() {
    int b = blockIdx.x;
    __shared__ uint32_t mw[78];
    __shared__ int pfx[79];
    __shared__ uint16_t klist[2450];
    int t = threadIdx.x;
    if (t < 39)            mw[t] = g_op2m[b][0][t];
    else if (t < 78)       mw[t] = g_op2m[b][1][t - 39];
    __syncthreads();
    if (t == 0) {
        int s = 0;
        for (int w = 0; w < 78; w++) { pfx[w] = s; s += __popc(mw[w]); }
        pfx[78] = s;
    }
    __syncthreads();
    if (t < 78) {
        uint32_t m = mw[t];
        int base = (t < 39 ? 0 : 1225) + (t < 39 ? t : t - 39) * 32;
        int o = pfx[t];
        while (m) { int j = __ffs(m) - 1; m &= m - 1; klist[o++] = (uint16_t)(base + j); }
    }
    __syncthreads();
    int nb = pfx[78];
    if (t < 200) {
        const float* col = g_wf0T + t;
        float acc = 0.f;
        int i = 0;
        for (; i + 8 <= nb; i += 8) {
            float v0 = __ldg(&col[(int)klist[i]     * 200]);
            float v1 = __ldg(&col[(int)klist[i + 1] * 200]);
            float v2 = __ldg(&col[(int)klist[i + 2] * 200]);
            float v3 = __ldg(&col[(int)klist[i + 3] * 200]);
            float v4 = __ldg(&col[(int)klist[i + 4] * 200]);
            float v5 = __ldg(&col[(int)klist[i + 5] * 200]);
            float v6 = __ldg(&col[(int)klist[i + 6] * 200]);
            float v7 = __ldg(&col[(int)klist[i + 7] * 200]);
            acc = __fadd_rn(acc, v0); acc = __fadd_rn(acc, v1);
            acc = __fadd_rn(acc, v2); acc = __fadd_rn(acc, v3);
            acc = __fadd_rn(acc, v4); acc = __fadd_rn(acc, v5);
            acc = __fadd_rn(acc, v6); acc = __fadd_rn(acc, v7);
        }
        for (; i < nb; i++) acc = __fadd_rn(acc, __ldg(&col[(int)klist[i] * 200]));
        int idx = b * 200 + t;
        float m = g_mf0[idx] + acc;
        float o = (m > 1.f) ? 1.f : 0.f;
        g_mf0[idx] = (m > 1.f) ? 0.f : m;
        g_tf0[idx] += o;
    }
}

// ---------------- final readout: out = (Tf0 @ wf1^T) / 100 ----------------
__global__ void k_final(const float* __restrict__ wf1, float* __restrict__ out) {
    int i = blockIdx.x * blockDim.x + threadIdx.x;
    if (i >= BN * 10) return;
    int b = i / 10, j = i % 10;
    const float* tf = &g_tf0[b * 200];
    const float* w  = &wf1[j * 200];
    float s = 0.f;
#pragma unroll 8
    for (int n = 0; n < 200; n++) s = __fmaf_rn(tf[n], w[n], s);
    out[i] = s / 100.0f;
}

// ---------------- launch ----------------
extern "C" void kernel_launch(void* const* d_in, const int* in_sizes, int n_in,
                              void* d_out, int out_size) {
    const float* in  = (const float*)d_in[0];
    const float* w1  = (const float*)d_in[1];
    const float* w2  = (const float*)d_in[2];
    const float* wf0 = (const float*)d_in[3];
    const float* wf1 = (const float*)d_in[4];
    float* out = (float*)d_out;

    cudaFuncSetAttribute(k_conv2, cudaFuncAttributeMaxDynamicSharedMemorySize, C2_SMEM);

    // Zero persistent state (graph-capturable async memsets)
    void* p;
    cudaGetSymbolAddress(&p, g_m1);  cudaMemsetAsync(p, 0, sizeof(float) * BN * 20 * 784);
    cudaGetSymbolAddress(&p, g_m1s); cudaMemsetAsync(p, 0, sizeof(float) * BN * 20 * 196);
    cudaGetSymbolAddress(&p, g_m2);  cudaMemsetAsync(p, 0, sizeof(float) * BN * 50 * 196);
    cudaGetSymbolAddress(&p, g_m2s); cudaMemsetAsync(p, 0, sizeof(float) * BN * 50 * 49);
    cudaGetSymbolAddress(&p, g_mf0); cudaMemsetAsync(p, 0, sizeof(float) * BN * 200);
    cudaGetSymbolAddress(&p, g_tf0); cudaMemsetAsync(p, 0, sizeof(float) * BN * 200);

    // One-time transposes (in-graph, before the step loop)
    k_prep<<<(2 * 500 * 26 + 2450 * 200 + 255) / 256, 256>>>(w2, wf0);

    // Per-step keys: JAX partitionable split — key_t = threefry((0,42), (0,t))
    uint32_t keys[NSTEPS][2];
    for (int t = 0; t < NSTEPS; t++)
        tf2x32(0u, 42u, 0u, (uint32_t)t, keys[t][0], keys[t][1]);

    for (int t = 0; t < NSTEPS; t++) {
        k_conv1<<<dim3(BN, 2), 224>>>(in, w1, keys[t][0], keys[t][1]);
        k_conv2<<<dim3(BN, 2), 256, C2_SMEM>>>();
        k_fc0s <<<BN, 256>>>();
    }
    k_final<<<(BN * 10 + 255) / 256, 256>>>(wf1, out);
}

// round 12
// speedup vs baseline: 1.2343x; 1.2343x over previous
#include <cuda_runtime.h>
#include <cstdint>

#define BN 512
#define NSTEPS 100
#define C2_SMEM ((364 + 13000) * 4)

// ---------------- persistent device state (allocation-free scratch) ----------------
__device__ float    g_m1 [BN * 20 * 784];   // conv1 membrane
__device__ float    g_m1s[BN * 20 * 196];   // pool1 membrane
__device__ uint32_t g_opm2[2][BN * 196];    // pool1 spike masks, double-buffered by step parity
__device__ float    g_m2 [BN * 50 * 196];   // conv2 membrane
__device__ float    g_m2s[BN * 50 * 49];    // pool2 membrane
__device__ uint32_t g_op2m2[2][BN][2][40];  // pool2 spike masks, double-buffered
__device__ float    g_mf0[BN * 200];        // fc0 membrane
__device__ float    g_tf0[BN * 200];        // fc0 total spike count (ONLY output that matters)
__device__ float    g_w2t [2 * 500 * 26];   // conv2 weights pre-transposed [cb][kk*20+ci][ch pad26]
__device__ float    g_wf0T[2450 * 200];     // wf0 transposed [k][n]

// ---------------- Threefry-2x32, 20 rounds (matches JAX exactly) ----------------
__host__ __device__ __forceinline__ void tf2x32(uint32_t k0, uint32_t k1,
                                                uint32_t x0, uint32_t x1,
                                                uint32_t& o0, uint32_t& o1) {
    uint32_t k2 = k0 ^ k1 ^ 0x1BD11BDAu;
    x0 += k0; x1 += k1;
#define TFR(r) { x0 += x1; x1 = (x1 << (r)) | (x1 >> (32 - (r))); x1 ^= x0; }
    TFR(13) TFR(15) TFR(26) TFR(6)   x0 += k1; x1 += k2 + 1u;
    TFR(17) TFR(29) TFR(16) TFR(24)  x0 += k2; x1 += k0 + 2u;
    TFR(13) TFR(15) TFR(26) TFR(6)   x0 += k0; x1 += k1 + 3u;
    TFR(17) TFR(29) TFR(16) TFR(24)  x0 += k1; x1 += k2 + 4u;
    TFR(13) TFR(15) TFR(26) TFR(6)   x0 += k2; x1 += k0 + 5u;
#undef TFR
    o0 = x0; o1 = x1;
}

// ---------------- one-time prep: transpose w2 and wf0 ----------------
__global__ void k_prep(const float* __restrict__ w2, const float* __restrict__ wf0) {
    int i = blockIdx.x * blockDim.x + threadIdx.x;
    if (i < 2 * 500 * 26) {
        int ch = i % 26, rem = i / 26, kkci = rem % 500, cb = rem / 500;
        int kk = kkci / 20, ci = kkci % 20;
        g_w2t[i] = (ch < 25) ? w2[(cb * 25 + ch) * 500 + ci * 25 + kk] : 0.f;
    }
    int j = i - 2 * 500 * 26;
    if (j >= 0 && j < 2450 * 200) {
        int n = j % 200, k = j / 200;
        g_wf0T[j] = wf0[n * 2450 + k];
    }
}

// ================= phase bodies (byte-identical math to round 10) =================

// ---- conv1 (RNG fused) + fire(1.0) + avgpool2 + fire(0.75); 256-thread strides ----
__device__ __forceinline__ void conv1_body(unsigned char* dyn,
                                           const float* __restrict__ in,
                                           const float* __restrict__ w1,
                                           uint32_t k0, uint32_t k1,
                                           int b, int par) {
    float (*sin_)[32] = (float(*)[32])dyn;          // 32x32 padded input
    float* sw = (float*)(dyn + 4096);               // 20x25 weights
    int t = threadIdx.x;
    for (int i = t; i < 1024; i += 256) ((float*)sin_)[i] = 0.f;
    for (int i = t; i < 500;  i += 256) sw[i] = w1[i];
    __syncthreads();
    for (int i = t; i < 784; i += 256) {
        uint32_t o0, o1;
        tf2x32(k0, k1, 0u, (uint32_t)(b * 784 + i), o0, o1);
        uint32_t bits = o0 ^ o1;
        float u = __uint_as_float((bits >> 9) | 0x3f800000u) - 1.0f;
        float v = in[b * 784 + i];
        float sgn = (v > 0.f) ? 1.f : ((v < 0.f) ? -1.f : 0.f);
        sin_[2 + i / 28][2 + i % 28] = (fabsf(v) * 0.5f > u) ? sgn : 0.f;
    }
    __syncthreads();

    if (t < 196) {
        int py = t / 14, px = t % 14;
        int r0 = 2 * py, c0 = 2 * px;
        float p[6][6];
#pragma unroll
        for (int r = 0; r < 6; r++)
#pragma unroll
            for (int c = 0; c < 6; c++) p[r][c] = sin_[r0 + r][c0 + c];

        uint32_t mask = 0u;
        for (int ch = 0; ch < 20; ch++) {
            const float* w = &sw[ch * 25];
            float a00 = 0.f, a01 = 0.f, a10 = 0.f, a11 = 0.f;
#pragma unroll
            for (int ky = 0; ky < 5; ky++)
#pragma unroll
                for (int kx = 0; kx < 5; kx++) {
                    float wv = w[ky * 5 + kx];
                    a00 = __fmaf_rn(p[ky][kx],         wv, a00);
                    a01 = __fmaf_rn(p[ky][kx + 1],     wv, a01);
                    a10 = __fmaf_rn(p[ky + 1][kx],     wv, a10);
                    a11 = __fmaf_rn(p[ky + 1][kx + 1], wv, a11);
                }
            size_t mb = (size_t)(b * 20 + ch) * 784;
            int i00 = r0 * 28 + c0;
            float m00 = g_m1[mb + i00]      + a00;
            float m01 = g_m1[mb + i00 + 1]  + a01;
            float m10 = g_m1[mb + i00 + 28] + a10;
            float m11 = g_m1[mb + i00 + 29] + a11;
            float f00 = (m00 > 1.f) ? 1.f : 0.f; g_m1[mb + i00]      = (m00 > 1.f) ? 0.f : m00;
            float f01 = (m01 > 1.f) ? 1.f : 0.f; g_m1[mb + i00 + 1]  = (m01 > 1.f) ? 0.f : m01;
            float f10 = (m10 > 1.f) ? 1.f : 0.f; g_m1[mb + i00 + 28] = (m10 > 1.f) ? 0.f : m10;
            float f11 = (m11 > 1.f) ? 1.f : 0.f; g_m1[mb + i00 + 29] = (m11 > 1.f) ? 0.f : m11;
            int pi = (b * 20 + ch) * 196 + t;
            float ms = g_m1s[pi] + 0.25f * (f00 + f01 + f10 + f11);
            if (ms > 0.75f) { mask |= (1u << ch); g_m1s[pi] = 0.f; }
            else            { g_m1s[pi] = ms; }
        }
        g_opm2[par][b * 196 + t] = mask;
    }
}

// ---- conv2 SPARSE, 2 images/block (round-10 exact) ----
__device__ __forceinline__ void conv2_body(unsigned char* dyn, int j, int par) {
    uint32_t* sm    = (uint32_t*)dyn;                // 18x18 spike masks (halo zero)
    uint32_t* smask = (uint32_t*)dyn + 324;          // 40-word output mask
    float*    swt   = (float*)(dyn + 364 * 4);       // [kk][ci][ch] slot 26
    int cb = j >> 8;
    int b0 = (j & 255) * 2;
    int t = threadIdx.x;
    {
        const float4* src = (const float4*)(g_w2t + cb * 13000);
        float4* dst = (float4*)swt;
        for (int i = t; i < 3250; i += 256) dst[i] = src[i];
    }

    for (int bi = 0; bi < 2; bi++) {
        int b = b0 + bi;
        __syncthreads();
        for (int i = t; i < 324; i += 256) {
            int rr = i / 18 - 2, cc = i % 18 - 2;
            sm[i] = (rr >= 0 && rr < 14 && cc >= 0 && cc < 14) ? g_opm2[par][b * 196 + rr * 14 + cc] : 0u;
        }
        if (t < 40) smask[t] = 0u;
        __syncthreads();

        if (t < 245) {
            int cog = t / 49, q = t % 49;
            int py = q / 7, px = q % 7;
            int r0 = 2 * py, c0 = 2 * px;
            float acc[5][4] = {};
#pragma unroll 1
            for (int ky = 0; ky < 5; ky++) {
                const uint32_t* mr0 = &sm[(r0 + ky) * 18 + c0];
                const uint32_t* mr1 = mr0 + 18;
#pragma unroll 1
                for (int kx = 0; kx < 5; kx++) {
                    uint32_t m0 = mr0[kx], m1 = mr0[kx + 1];
                    uint32_t m2 = mr1[kx], m3 = mr1[kx + 1];
                    const float* wk = &swt[(ky * 5 + kx) * 20 * 26 + cog * 5];
                    while (m0) {
                        int ci = __ffs(m0) - 1; m0 &= m0 - 1;
                        const float* w = wk + ci * 26;
                        acc[0][0] = __fadd_rn(acc[0][0], w[0]);
                        acc[1][0] = __fadd_rn(acc[1][0], w[1]);
                        acc[2][0] = __fadd_rn(acc[2][0], w[2]);
                        acc[3][0] = __fadd_rn(acc[3][0], w[3]);
                        acc[4][0] = __fadd_rn(acc[4][0], w[4]);
                    }
                    while (m1) {
                        int ci = __ffs(m1) - 1; m1 &= m1 - 1;
                        const float* w = wk + ci * 26;
                        acc[0][1] = __fadd_rn(acc[0][1], w[0]);
                        acc[1][1] = __fadd_rn(acc[1][1], w[1]);
                        acc[2][1] = __fadd_rn(acc[2][1], w[2]);
                        acc[3][1] = __fadd_rn(acc[3][1], w[3]);
                        acc[4][1] = __fadd_rn(acc[4][1], w[4]);
                    }
                    while (m2) {
                        int ci = __ffs(m2) - 1; m2 &= m2 - 1;
                        const float* w = wk + ci * 26;
                        acc[0][2] = __fadd_rn(acc[0][2], w[0]);
                        acc[1][2] = __fadd_rn(acc[1][2], w[1]);
                        acc[2][2] = __fadd_rn(acc[2][2], w[2]);
                        acc[3][2] = __fadd_rn(acc[3][2], w[3]);
                        acc[4][2] = __fadd_rn(acc[4][2], w[4]);
                    }
                    while (m3) {
                        int ci = __ffs(m3) - 1; m3 &= m3 - 1;
                        const float* w = wk + ci * 26;
                        acc[0][3] = __fadd_rn(acc[0][3], w[0]);
                        acc[1][3] = __fadd_rn(acc[1][3], w[1]);
                        acc[2][3] = __fadd_rn(acc[2][3], w[2]);
                        acc[3][3] = __fadd_rn(acc[3][3], w[3]);
                        acc[4][3] = __fadd_rn(acc[4][3], w[4]);
                    }
                }
            }
#pragma unroll
            for (int u = 0; u < 5; u++) {
                int colocal = cog * 5 + u;
                int co = cb * 25 + colocal;
                size_t mb = (size_t)(b * 50 + co) * 196;
                int i00 = r0 * 14 + c0;
                float m00 = g_m2[mb + i00]      + acc[u][0];
                float m01 = g_m2[mb + i00 + 1]  + acc[u][1];
                float m10 = g_m2[mb + i00 + 14] + acc[u][2];
                float m11 = g_m2[mb + i00 + 15] + acc[u][3];
                float f00 = (m00 > 1.f) ? 1.f : 0.f; g_m2[mb + i00]      = (m00 > 1.f) ? 0.f : m00;
                float f01 = (m01 > 1.f) ? 1.f : 0.f; g_m2[mb + i00 + 1]  = (m01 > 1.f) ? 0.f : m01;
                float f10 = (m10 > 1.f) ? 1.f : 0.f; g_m2[mb + i00 + 14] = (m10 > 1.f) ? 0.f : m10;
                float f11 = (m11 > 1.f) ? 1.f : 0.f; g_m2[mb + i00 + 15] = (m11 > 1.f) ? 0.f : m11;
                int pi = (b * 50 + co) * 49 + q;
                float ms = g_m2s[pi] + 0.25f * (f00 + f01 + f10 + f11);
                if (ms > 0.75f) {
                    g_m2s[pi] = 0.f;
                    int bit = colocal * 49 + q;
                    atomicOr(&smask[bit >> 5], 1u << (bit & 31));
                } else {
                    g_m2s[pi] = ms;
                }
            }
        }
        __syncthreads();
        if (t < 39) g_op2m2[par][b][cb][t] = smask[t];
    }
}

// ---- fc0 SPARSE + fused fire (round-10 exact) ----
__device__ __forceinline__ void fc0_body(unsigned char* dyn, int b, int par) {
    uint32_t* mw    = (uint32_t*)dyn;                 // 78 words
    int*      pfx   = (int*)(dyn + 320);              // 79 ints
    uint16_t* klist = (uint16_t*)(dyn + 320 + 320);   // 2450 entries
    int t = threadIdx.x;
    if (t < 39)            mw[t] = g_op2m2[par][b][0][t];
    else if (t < 78)       mw[t] = g_op2m2[par][b][1][t - 39];
    __syncthreads();
    if (t == 0) {
        int s = 0;
        for (int w = 0; w < 78; w++) { pfx[w] = s; s += __popc(mw[w]); }
        pfx[78] = s;
    }
    __syncthreads();
    if (t < 78) {
        uint32_t m = mw[t];
        int base = (t < 39 ? 0 : 1225) + (t < 39 ? t : t - 39) * 32;
        int o = pfx[t];
        while (m) { int j = __ffs(m) - 1; m &= m - 1; klist[o++] = (uint16_t)(base + j); }
    }
    __syncthreads();
    int nb = pfx[78];
    if (t < 200) {
        const float* col = g_wf0T + t;
        float acc = 0.f;
        int i = 0;
        for (; i + 8 <= nb; i += 8) {
            float v0 = __ldg(&col[(int)klist[i]     * 200]);
            float v1 = __ldg(&col[(int)klist[i + 1] * 200]);
            float v2 = __ldg(&col[(int)klist[i + 2] * 200]);
            float v3 = __ldg(&col[(int)klist[i + 3] * 200]);
            float v4 = __ldg(&col[(int)klist[i + 4] * 200]);
            float v5 = __ldg(&col[(int)klist[i + 5] * 200]);
            float v6 = __ldg(&col[(int)klist[i + 6] * 200]);
            float v7 = __ldg(&col[(int)klist[i + 7] * 200]);
            acc = __fadd_rn(acc, v0); acc = __fadd_rn(acc, v1);
            acc = __fadd_rn(acc, v2); acc = __fadd_rn(acc, v3);
            acc = __fadd_rn(acc, v4); acc = __fadd_rn(acc, v5);
            acc = __fadd_rn(acc, v6); acc = __fadd_rn(acc, v7);
        }
        for (; i < nb; i++) acc = __fadd_rn(acc, __ldg(&col[(int)klist[i] * 200]));
        int idx = b * 200 + t;
        float m = g_mf0[idx] + acc;
        float o = (m > 1.f) ? 1.f : 0.f;
        g_mf0[idx] = (m > 1.f) ? 0.f : m;
        g_tf0[idx] += o;
    }
}

// ---------------- fused pipelined step: conv1(s) | conv2(s-1) | fc0(s-2) ----------------
// 1536 blocks, type = bid % 3 (interleaved so every SM wave mixes phases).
__global__ __launch_bounds__(256) void k_step(const float* __restrict__ in,
                                              const float* __restrict__ w1,
                                              uint32_t k0, uint32_t k1, int s) {
    extern __shared__ unsigned char dyn[];
    int bid = blockIdx.x;
    int type = bid % 3;
    int idx  = bid / 3;
    if (type == 0) {
        if (s < NSTEPS) conv1_body(dyn, in, w1, k0, k1, idx, s & 1);
    } else if (type == 1) {
        int t2 = s - 1;
        if (t2 >= 0 && t2 < NSTEPS) conv2_body(dyn, idx, t2 & 1);
    } else {
        int t3 = s - 2;
        if (t3 >= 0 && t3 < NSTEPS) fc0_body(dyn, idx, t3 & 1);
    }
}

// ---------------- final readout: out = (Tf0 @ wf1^T) / 100 ----------------
__global__ void k_final(const float* __restrict__ wf1, float* __restrict__ out) {
    int i = blockIdx.x * blockDim.x + threadIdx.x;
    if (i >= BN * 10) return;
    int b = i / 10, j = i % 10;
    const float* tf = &g_tf0[b * 200];
    const float* w  = &wf1[j * 200];
    float s = 0.f;
#pragma unroll 8
    for (int n = 0; n < 200; n++) s = __fmaf_rn(tf[n], w[n], s);
    out[i] = s / 100.0f;
}

// ---------------- launch ----------------
extern "C" void kernel_launch(void* const* d_in, const int* in_sizes, int n_in,
                              void* d_out, int out_size) {
    const float* in  = (const float*)d_in[0];
    const float* w1  = (const float*)d_in[1];
    const float* w2  = (const float*)d_in[2];
    const float* wf0 = (const float*)d_in[3];
    const float* wf1 = (const float*)d_in[4];
    float* out = (float*)d_out;

    cudaFuncSetAttribute(k_step, cudaFuncAttributeMaxDynamicSharedMemorySize, C2_SMEM);

    // Zero persistent state (graph-capturable async memsets)
    void* p;
    cudaGetSymbolAddress(&p, g_m1);  cudaMemsetAsync(p, 0, sizeof(float) * BN * 20 * 784);
    cudaGetSymbolAddress(&p, g_m1s); cudaMemsetAsync(p, 0, sizeof(float) * BN * 20 * 196);
    cudaGetSymbolAddress(&p, g_m2);  cudaMemsetAsync(p, 0, sizeof(float) * BN * 50 * 196);
    cudaGetSymbolAddress(&p, g_m2s); cudaMemsetAsync(p, 0, sizeof(float) * BN * 50 * 49);
    cudaGetSymbolAddress(&p, g_mf0); cudaMemsetAsync(p, 0, sizeof(float) * BN * 200);
    cudaGetSymbolAddress(&p, g_tf0); cudaMemsetAsync(p, 0, sizeof(float) * BN * 200);

    // One-time transposes (in-graph, before the step loop)
    k_prep<<<(2 * 500 * 26 + 2450 * 200 + 255) / 256, 256>>>(w2, wf0);

    // Per-step keys: JAX partitionable split — key_t = threefry((0,42), (0,t))
    uint32_t keys[NSTEPS][2];
    for (int t = 0; t < NSTEPS; t++)
        tf2x32(0u, 42u, 0u, (uint32_t)t, keys[t][0], keys[t][1]);

    // Pipelined: slot s runs conv1(s), conv2(s-1), fc0(s-2)
    for (int s = 0; s < NSTEPS + 2; s++) {
        uint32_t kk0 = (s < NSTEPS) ? keys[s][0] : 0u;
        uint32_t kk1 = (s < NSTEPS) ? keys[s][1] : 0u;
        k_step<<<1536, 256, C2_SMEM>>>(in, w1, kk0, kk1, s);
    }
    k_final<<<(BN * 10 + 255) / 256, 256>>>(wf1, out);
}